// round 13
// baseline (speedup 1.0000x reference)
#include <cuda_runtime.h>
#include <cuda_fp16.h>

// preds [B=8, N=16, C=4, H=128, W=256] f32, gt [8,4,128,256] f32, out scalar f32
#define CHW      131072
#define NCHW     (16 * CHW)
#define NPIX     1048576
#define GRID     296                // 2 CTAs/SM: one persistent wave
#define NTHR     256
#define TILE_PX  1024               // 256 threads * 4 px (float4)
#define NTILES   1024               // NPIX / TILE_PX; 128 tiles per batch image

__device__ float        g_partials[GRID];
__device__ unsigned int g_done = 0;

// Exact packed compare-and-swap on 2 fp16 values (HMNMX2, alu pipe, rt=2)
__device__ __forceinline__ void cash(__half2 &a, __half2 &b) {
    const __half2 lo = __hmin2(a, b);
    const __half2 hi = __hmax2(a, b);
    a = lo; b = hi;
}

// Green's 16-input 60-comparator sorting network on half2
__device__ __forceinline__ void sort16h(__half2 v[16]) {
    cash(v[0],v[1]);  cash(v[2],v[3]);  cash(v[4],v[5]);  cash(v[6],v[7]);
    cash(v[8],v[9]);  cash(v[10],v[11]);cash(v[12],v[13]);cash(v[14],v[15]);
    cash(v[0],v[2]);  cash(v[4],v[6]);  cash(v[8],v[10]); cash(v[12],v[14]);
    cash(v[1],v[3]);  cash(v[5],v[7]);  cash(v[9],v[11]); cash(v[13],v[15]);
    cash(v[0],v[4]);  cash(v[8],v[12]); cash(v[1],v[5]);  cash(v[9],v[13]);
    cash(v[2],v[6]);  cash(v[10],v[14]);cash(v[3],v[7]);  cash(v[11],v[15]);
    cash(v[0],v[8]);  cash(v[1],v[9]);  cash(v[2],v[10]); cash(v[3],v[11]);
    cash(v[4],v[12]); cash(v[5],v[13]); cash(v[6],v[14]); cash(v[7],v[15]);
    cash(v[5],v[10]); cash(v[6],v[9]);  cash(v[3],v[12]); cash(v[13],v[14]);
    cash(v[7],v[11]); cash(v[1],v[2]);  cash(v[4],v[8]);
    cash(v[1],v[4]);  cash(v[7],v[13]); cash(v[2],v[8]);  cash(v[11],v[14]);
    cash(v[5],v[6]);  cash(v[9],v[10]);
    cash(v[2],v[4]);  cash(v[11],v[13]);cash(v[3],v[8]);  cash(v[7],v[12]);
    cash(v[6],v[8]);  cash(v[10],v[12]);cash(v[3],v[5]);  cash(v[7],v[9]);
    cash(v[3],v[4]);  cash(v[5],v[6]);  cash(v[7],v[8]);  cash(v[9],v[10]);
    cash(v[11],v[12]);
    cash(v[6],v[7]);  cash(v[8],v[9]);
}

// Issue this thread's 17 LDG.128 for tile tg into staging regs
__device__ __forceinline__ void load_tile(const float* __restrict__ preds,
                                          const float* __restrict__ gt,
                                          int tg, int tid, float4* v, float4& g) {
    const int b   = tg >> 7;                    // 128 tiles per image
    const int off = ((tg & 127) << 8) + tid;    // float4 index within [C,H,W]
    const float4* ps = reinterpret_cast<const float4*>(preds) + ((b * NCHW) >> 2) + off;
    #pragma unroll
    for (int n = 0; n < 16; n++) v[n] = ps[(n * CHW) >> 2];
    g = reinterpret_cast<const float4*>(gt)[((b * CHW) >> 2) + off];
}

__global__ __launch_bounds__(NTHR, 2) void crps_pipe(const float* __restrict__ preds,
                                                     const float* __restrict__ gt,
                                                     float* __restrict__ out) {
    const int tid = threadIdx.x;
    const int bid = blockIdx.x;
    const int nt  = (NTILES - bid + GRID - 1) / GRID;   // 3 or 4 tiles

    float4 v[16], g;
    float  acc = 0.f;

    // Prologue: stage tile 0 (only fully-exposed latency)
    load_tile(preds, gt, bid, tid, v, g);

    for (int i = 0; i < nt; i++) {
        // Drain staging: term1 (f32, fma pipe) + pack to half2 working set
        float4 t1 = make_float4(0.f, 0.f, 0.f, 0.f);
        __half2 ha[16], hb[16];
        #pragma unroll
        for (int n = 0; n < 16; n++) {
            t1.x += fabsf(v[n].x - g.x);
            t1.y += fabsf(v[n].y - g.y);
            t1.z += fabsf(v[n].z - g.z);
            t1.w += fabsf(v[n].w - g.w);
            ha[n] = __floats2half2_rn(v[n].x, v[n].y);
            hb[n] = __floats2half2_rn(v[n].z, v[n].w);
        }
        const float t1s = t1.x + t1.y + t1.z + t1.w;

        // Staging regs free -> issue next tile's 17 LDG.128 NOW;
        // the 240-op sort below is the latency blanket
        if (i + 1 < nt) load_tile(preds, gt, bid + (i + 1) * GRID, tid, v, g);

        // Sort (exact on f16-rounded values) + term2
        sort16h(ha);
        sort16h(hb);
        float4 t2 = make_float4(0.f, 0.f, 0.f, 0.f);
        #pragma unroll
        for (int k = 0; k < 8; k++) {
            const float w = (float)(2 * k - 15);
            const float2 da = __half22float2(__hsub2(ha[k], ha[15 - k]));
            const float2 db = __half22float2(__hsub2(hb[k], hb[15 - k]));
            t2.x = fmaf(w, da.x, t2.x);
            t2.y = fmaf(w, da.y, t2.y);
            t2.z = fmaf(w, db.x, t2.z);
            t2.w = fmaf(w, db.y, t2.w);
        }

        const float c1 = 1.0f / (16.0f * (float)NPIX);
        const float c2 = 1.0f / (240.0f * (float)NPIX);    // N*(N-1) = 240
        acc += t1s * c1 - (t2.x + t2.y + t2.z + t2.w) * c2;
    }

    // Deterministic block reduction (8 warps)
    #pragma unroll
    for (int o = 16; o > 0; o >>= 1) acc += __shfl_down_sync(0xffffffffu, acc, o);
    __shared__ float s[NTHR / 32];
    if ((tid & 31) == 0) s[tid >> 5] = acc;
    __syncthreads();
    if (tid < 32) {
        float x = (tid < (NTHR / 32)) ? s[tid] : 0.f;
        #pragma unroll
        for (int o = 4; o > 0; o >>= 1) x += __shfl_down_sync(0xffu, x, o);
        if (tid == 0) g_partials[bid] = x;
    }

    // Fused last-block final reduction (deterministic order; atomic only elects)
    __shared__ bool s_last;
    __threadfence();
    if (tid == 0) {
        unsigned int r = atomicAdd(&g_done, 1u);
        s_last = (r == (unsigned)(GRID - 1));
    }
    __syncthreads();
    if (s_last) {
        float a2 = __ldcg(&g_partials[tid]);                          // 0..255
        if (tid < GRID - NTHR) a2 += __ldcg(&g_partials[tid + NTHR]); // 256..295
        #pragma unroll
        for (int o = 16; o > 0; o >>= 1) a2 += __shfl_down_sync(0xffffffffu, a2, o);
        __shared__ float s2[NTHR / 32];
        if ((tid & 31) == 0) s2[tid >> 5] = a2;
        __syncthreads();
        if (tid == 0) {
            out[0] = s2[0] + s2[1] + s2[2] + s2[3]
                   + s2[4] + s2[5] + s2[6] + s2[7];
            g_done = 0;                                 // reset for next graph replay
        }
    }
}

extern "C" void kernel_launch(void* const* d_in, const int* in_sizes, int n_in,
                              void* d_out, int out_size) {
    const float* preds = (const float*)d_in[0];  // [8,16,4,128,256]
    const float* gt    = (const float*)d_in[1];  // [8,4,128,256]
    float* out = (float*)d_out;                  // scalar f32
    (void)in_sizes; (void)n_in; (void)out_size;
    crps_pipe<<<GRID, NTHR>>>(preds, gt, out);
}